// round 1
// baseline (speedup 1.0000x reference)
#include <cuda_runtime.h>

#define NB 2048
#define NF 4096
#define NC 8192
#define NT 8
#define NK 1024
#define NS 8
#define MB 4          // batch rows per CTA
#define THREADS 512

// Flattened literal table: for (k,s,t) -> byte offset into smem tile.
// off = feat*32 + (sign>0 ? 0 : 16); smem layout is [feat][variant][4 rows] fp32,
// variant 0 = x, variant 1 = 1-x.  256 KB static device scratch (allowed).
__device__ int g_off[NK * NS * NT];

__global__ void prep_kernel(const int* __restrict__ conj_feat,
                            const int* __restrict__ conj_sign,
                            const int* __restrict__ class_conj) {
    int i = blockIdx.x * blockDim.x + threadIdx.x;
    if (i >= NK * NS * NT) return;
    int k = i >> 6;        // / (S*T)
    int j = i & 63;
    int s = j >> 3;
    int t = j & 7;
    int c    = class_conj[k * NS + s];
    int feat = conj_feat[c * NT + t];
    int sign = conj_sign[c * NT + t];
    g_off[i] = feat * 32 + (sign > 0 ? 0 : 16);
}

static __device__ __forceinline__ float4 mul4(float4 a, float4 b) {
    a.x *= b.x; a.y *= b.y; a.z *= b.z; a.w *= b.w;
    return a;
}
static __device__ __forceinline__ float4 max4(float4 a, float4 b) {
    a.x = fmaxf(a.x, b.x); a.y = fmaxf(a.y, b.y);
    a.z = fmaxf(a.z, b.z); a.w = fmaxf(a.w, b.w);
    return a;
}

__global__ void __launch_bounds__(THREADS, 1)
dnf_kernel(const float* __restrict__ x, float* __restrict__ out) {
    extern __shared__ float smem[];   // [4096][2][4] fp32 = 128 KB
    const int b0 = blockIdx.x * MB;

    // Phase A: stage x and 1-x, transposed so 4 rows are contiguous per feat.
    for (int i = threadIdx.x; i < MB * NF; i += THREADS) {
        int r = i >> 12;           // row 0..3
        int f = i & (NF - 1);      // feature (coalesced across lanes)
        float v = x[(size_t)(b0 + r) * NF + f];
        smem[f * 8 + r]     = v;
        smem[f * 8 + 4 + r] = 1.0f - v;
    }
    __syncthreads();

    const char* sb = (const char*)smem;

    // Phase B: each thread computes out[b0..b0+3][k] for its k values.
    for (int kk = 0; kk < NK; kk += THREADS) {
        int k = kk + threadIdx.x;
        const int4* tp = (const int4*)(g_off + k * (NS * NT));
        float4 mx = make_float4(0.f, 0.f, 0.f, 0.f);  // products are >= 0

        #pragma unroll
        for (int s = 0; s < NS; s++) {
            int4 oa = tp[2 * s];
            int4 ob = tp[2 * s + 1];
            float4 v0 = *(const float4*)(sb + oa.x);
            float4 v1 = *(const float4*)(sb + oa.y);
            float4 v2 = *(const float4*)(sb + oa.z);
            float4 v3 = *(const float4*)(sb + oa.w);
            float4 v4 = *(const float4*)(sb + ob.x);
            float4 v5 = *(const float4*)(sb + ob.y);
            float4 v6 = *(const float4*)(sb + ob.z);
            float4 v7 = *(const float4*)(sb + ob.w);
            // tree multiply: dep chain depth 3 (12 cyc) instead of 7 (28 cyc)
            float4 p01 = mul4(v0, v1);
            float4 p23 = mul4(v2, v3);
            float4 p45 = mul4(v4, v5);
            float4 p67 = mul4(v6, v7);
            float4 p = mul4(mul4(p01, p23), mul4(p45, p67));
            mx = max4(mx, p);
        }

        out[(size_t)(b0 + 0) * NK + k] = mx.x;
        out[(size_t)(b0 + 1) * NK + k] = mx.y;
        out[(size_t)(b0 + 2) * NK + k] = mx.z;
        out[(size_t)(b0 + 3) * NK + k] = mx.w;
    }
}

extern "C" void kernel_launch(void* const* d_in, const int* in_sizes, int n_in,
                              void* d_out, int out_size) {
    const float* x  = (const float*)d_in[0];
    const int*   cf = (const int*)d_in[1];
    const int*   cs = (const int*)d_in[2];
    const int*   cc = (const int*)d_in[3];
    float* out = (float*)d_out;

    prep_kernel<<<(NK * NS * NT + 255) / 256, 256>>>(cf, cs, cc);

    size_t smem_bytes = (size_t)MB * NF * 2 * sizeof(float);  // 131072
    cudaFuncSetAttribute(dnf_kernel,
                         cudaFuncAttributeMaxDynamicSharedMemorySize,
                         (int)smem_bytes);
    dnf_kernel<<<NB / MB, THREADS, smem_bytes>>>(x, out);
}

// round 2
// speedup vs baseline: 1.2754x; 1.2754x over previous
#include <cuda_runtime.h>

#define NB 2048
#define NF 4096
#define NC 8192
#define NT 8
#define NK 1024
#define NS 8
#define MB 4            // batch rows per CTA
#define THREADS 1024    // one k per thread

// 16-bit slot table: slot = feat*2 + (sign>0 ? 0 : 1); smem byte addr = slot*16.
// smem layout: [feat][variant][4 rows] fp32 (16 B per (feat,variant) slot).
__device__ unsigned short g_slot[NK * NS * NT];   // 128 KB

__global__ void prep_kernel(const int* __restrict__ conj_feat,
                            const int* __restrict__ conj_sign,
                            const int* __restrict__ class_conj) {
    int i = blockIdx.x * blockDim.x + threadIdx.x;
    if (i >= NK * NS * NT) return;
    int k = i >> 6;
    int j = i & 63;
    int s = j >> 3;
    int t = j & 7;
    int c    = class_conj[k * NS + s];
    int feat = conj_feat[c * NT + t];
    int sign = conj_sign[c * NT + t];
    g_slot[i] = (unsigned short)(feat * 2 + (sign > 0 ? 0 : 1));
}

static __device__ __forceinline__ float4 mul4(float4 a, float4 b) {
    a.x *= b.x; a.y *= b.y; a.z *= b.z; a.w *= b.w;
    return a;
}
static __device__ __forceinline__ float4 max4(float4 a, float4 b) {
    a.x = fmaxf(a.x, b.x); a.y = fmaxf(a.y, b.y);
    a.z = fmaxf(a.z, b.z); a.w = fmaxf(a.w, b.w);
    return a;
}
static __device__ __forceinline__ const float4* slotp(const char* sb, unsigned u, int hi) {
    unsigned off = hi ? ((u >> 16) << 4) : ((u & 0xFFFFu) << 4);
    return (const float4*)(sb + off);
}

__global__ void __launch_bounds__(THREADS, 1)
dnf_kernel(const float* __restrict__ x, float* __restrict__ out) {
    extern __shared__ float smem[];   // [4096][2][4] fp32 = 128 KB
    const int b0 = blockIdx.x * MB;

    // Phase A: stage x and 1-x, transposed. r-inner mapping -> 2-way STS
    // conflicts instead of 8-way.
    for (int i = threadIdx.x; i < MB * NF; i += THREADS) {
        int r = i & (MB - 1);
        int f = i >> 2;
        float v = x[(size_t)(b0 + r) * NF + f];
        smem[f * 8 + r]     = v;
        smem[f * 8 + 4 + r] = 1.0f - v;
    }
    __syncthreads();

    const char* sb = (const char*)smem;
    const int k = threadIdx.x;                       // NK == THREADS
    const uint4* tp = (const uint4*)(g_slot + k * (NS * NT));  // 8 uint4, one per s

    uint4 tc = tp[0];                                // table for s=0
    float4 mx = make_float4(0.f, 0.f, 0.f, 0.f);     // products are >= 0

    #pragma unroll
    for (int s = 0; s < NS; s++) {
        uint4 tn;
        if (s < NS - 1) tn = tp[s + 1];              // prefetch next s's 8 slots

        float4 v0 = *slotp(sb, tc.x, 0);
        float4 v1 = *slotp(sb, tc.x, 1);
        float4 v2 = *slotp(sb, tc.y, 0);
        float4 v3 = *slotp(sb, tc.y, 1);
        float4 v4 = *slotp(sb, tc.z, 0);
        float4 v5 = *slotp(sb, tc.z, 1);
        float4 v6 = *slotp(sb, tc.w, 0);
        float4 v7 = *slotp(sb, tc.w, 1);

        float4 p = mul4(mul4(mul4(v0, v1), mul4(v2, v3)),
                        mul4(mul4(v4, v5), mul4(v6, v7)));
        mx = max4(mx, p);
        if (s < NS - 1) tc = tn;
    }

    out[(size_t)(b0 + 0) * NK + k] = mx.x;
    out[(size_t)(b0 + 1) * NK + k] = mx.y;
    out[(size_t)(b0 + 2) * NK + k] = mx.z;
    out[(size_t)(b0 + 3) * NK + k] = mx.w;
}

extern "C" void kernel_launch(void* const* d_in, const int* in_sizes, int n_in,
                              void* d_out, int out_size) {
    const float* x  = (const float*)d_in[0];
    const int*   cf = (const int*)d_in[1];
    const int*   cs = (const int*)d_in[2];
    const int*   cc = (const int*)d_in[3];
    float* out = (float*)d_out;

    prep_kernel<<<(NK * NS * NT + 255) / 256, 256>>>(cf, cs, cc);

    size_t smem_bytes = (size_t)MB * NF * 2 * sizeof(float);  // 131072
    cudaFuncSetAttribute(dnf_kernel,
                         cudaFuncAttributeMaxDynamicSharedMemorySize,
                         (int)smem_bytes);
    dnf_kernel<<<NB / MB, THREADS, smem_bytes>>>(x, out);
}

// round 3
// speedup vs baseline: 2.4439x; 1.9162x over previous
#include <cuda_runtime.h>
#include <cuda_fp16.h>

#define NB 2048
#define NF 4096
#define NC 8192
#define NT 8
#define NK 1024
#define NS 8
#define MB 8            // batch rows per CTA (fp16, 8 rows per 16B slot)
#define THREADS 1024    // one k per thread

// 16-bit slot table: slot = feat*2 + (sign>0 ? 0 : 1); smem byte addr = slot*16.
// smem layout: [feat][variant][8 rows] fp16 (16 B per (feat,variant) slot).
__device__ unsigned short g_slot[NK * NS * NT];   // 128 KB

__global__ void prep_kernel(const int* __restrict__ conj_feat,
                            const int* __restrict__ conj_sign,
                            const int* __restrict__ class_conj) {
    int i = blockIdx.x * blockDim.x + threadIdx.x;
    if (i >= NK * NS * NT) return;
    int k = i >> 6;
    int j = i & 63;
    int s = j >> 3;
    int t = j & 7;
    int c    = class_conj[k * NS + s];
    int feat = conj_feat[c * NT + t];
    int sign = conj_sign[c * NT + t];
    g_slot[i] = (unsigned short)(feat * 2 + (sign > 0 ? 0 : 1));
}

static __device__ __forceinline__ unsigned hmul2u(unsigned a, unsigned b) {
    __half2 ha = *reinterpret_cast<__half2*>(&a);
    __half2 hb = *reinterpret_cast<__half2*>(&b);
    __half2 hr = __hmul2(ha, hb);
    return *reinterpret_cast<unsigned*>(&hr);
}
static __device__ __forceinline__ unsigned hmax2u(unsigned a, unsigned b) {
    __half2 ha = *reinterpret_cast<__half2*>(&a);
    __half2 hb = *reinterpret_cast<__half2*>(&b);
    __half2 hr = __hmax2(ha, hb);
    return *reinterpret_cast<unsigned*>(&hr);
}
static __device__ __forceinline__ uint4 mulh8(uint4 a, uint4 b) {
    a.x = hmul2u(a.x, b.x); a.y = hmul2u(a.y, b.y);
    a.z = hmul2u(a.z, b.z); a.w = hmul2u(a.w, b.w);
    return a;
}
static __device__ __forceinline__ uint4 maxh8(uint4 a, uint4 b) {
    a.x = hmax2u(a.x, b.x); a.y = hmax2u(a.y, b.y);
    a.z = hmax2u(a.z, b.z); a.w = hmax2u(a.w, b.w);
    return a;
}
static __device__ __forceinline__ unsigned pack2(float a, float b) {
    __half2 h = __floats2half2_rn(a, b);
    return *reinterpret_cast<unsigned*>(&h);
}

__global__ void __launch_bounds__(THREADS, 1)
dnf_kernel(const float* __restrict__ x, float* __restrict__ out) {
    extern __shared__ unsigned smem_u[];   // [4096 feat][2 var][4 x u32] = 128 KB
    const int b0 = blockIdx.x * MB;

    // Phase A: each thread builds complete 16B slots for feats it owns:
    // 8 coalesced row loads -> pack fp16 -> 2 conflict-free STS.128.
    uint4* slots = (uint4*)smem_u;
    for (int f = threadIdx.x; f < NF; f += THREADS) {
        float v[MB];
        #pragma unroll
        for (int r = 0; r < MB; r++)
            v[r] = x[(size_t)(b0 + r) * NF + f];
        uint4 hx, hn;
        hx.x = pack2(v[0], v[1]);               hn.x = pack2(1.f - v[0], 1.f - v[1]);
        hx.y = pack2(v[2], v[3]);               hn.y = pack2(1.f - v[2], 1.f - v[3]);
        hx.z = pack2(v[4], v[5]);               hn.z = pack2(1.f - v[4], 1.f - v[5]);
        hx.w = pack2(v[6], v[7]);               hn.w = pack2(1.f - v[6], 1.f - v[7]);
        slots[f * 2]     = hx;
        slots[f * 2 + 1] = hn;
    }
    __syncthreads();

    const char* sb = (const char*)smem_u;
    const int k = threadIdx.x;                       // NK == THREADS
    const uint4* tp = (const uint4*)(g_slot + k * (NS * NT));  // 8 uint4, one per s

    uint4 tc = tp[0];                                // slots for s=0
    uint4 mx = make_uint4(0u, 0u, 0u, 0u);           // fp16 products >= 0

    #pragma unroll
    for (int s = 0; s < NS; s++) {
        uint4 tn;
        if (s < NS - 1) tn = tp[s + 1];              // prefetch next s's 8 slots

        uint4 q0 = *(const uint4*)(sb + ((tc.x & 0xFFFFu) << 4));
        uint4 q1 = *(const uint4*)(sb + ((tc.x >> 16)     << 4));
        uint4 q2 = *(const uint4*)(sb + ((tc.y & 0xFFFFu) << 4));
        uint4 q3 = *(const uint4*)(sb + ((tc.y >> 16)     << 4));
        uint4 q4 = *(const uint4*)(sb + ((tc.z & 0xFFFFu) << 4));
        uint4 q5 = *(const uint4*)(sb + ((tc.z >> 16)     << 4));
        uint4 q6 = *(const uint4*)(sb + ((tc.w & 0xFFFFu) << 4));
        uint4 q7 = *(const uint4*)(sb + ((tc.w >> 16)     << 4));

        uint4 p = mulh8(mulh8(mulh8(q0, q1), mulh8(q2, q3)),
                        mulh8(mulh8(q4, q5), mulh8(q6, q7)));
        mx = maxh8(mx, p);
        if (s < NS - 1) tc = tn;
    }

    // Unpack 8 rows and store (coalesced: lanes = consecutive k).
    float2 r01 = __half22float2(*reinterpret_cast<__half2*>(&mx.x));
    float2 r23 = __half22float2(*reinterpret_cast<__half2*>(&mx.y));
    float2 r45 = __half22float2(*reinterpret_cast<__half2*>(&mx.z));
    float2 r67 = __half22float2(*reinterpret_cast<__half2*>(&mx.w));
    out[(size_t)(b0 + 0) * NK + k] = r01.x;
    out[(size_t)(b0 + 1) * NK + k] = r01.y;
    out[(size_t)(b0 + 2) * NK + k] = r23.x;
    out[(size_t)(b0 + 3) * NK + k] = r23.y;
    out[(size_t)(b0 + 4) * NK + k] = r45.x;
    out[(size_t)(b0 + 5) * NK + k] = r45.y;
    out[(size_t)(b0 + 6) * NK + k] = r67.x;
    out[(size_t)(b0 + 7) * NK + k] = r67.y;
}

extern "C" void kernel_launch(void* const* d_in, const int* in_sizes, int n_in,
                              void* d_out, int out_size) {
    const float* x  = (const float*)d_in[0];
    const int*   cf = (const int*)d_in[1];
    const int*   cs = (const int*)d_in[2];
    const int*   cc = (const int*)d_in[3];
    float* out = (float*)d_out;

    prep_kernel<<<(NK * NS * NT + 255) / 256, 256>>>(cf, cs, cc);

    size_t smem_bytes = (size_t)NF * 2 * MB * sizeof(__half);  // 131072
    cudaFuncSetAttribute(dnf_kernel,
                         cudaFuncAttributeMaxDynamicSharedMemorySize,
                         (int)smem_bytes);
    dnf_kernel<<<NB / MB, THREADS, smem_bytes>>>(x, out);
}

// round 6
// speedup vs baseline: 2.9872x; 1.2223x over previous
#include <cuda_runtime.h>
#include <cuda_fp16.h>

#define NB 2048
#define NF 4096
#define NC 8192
#define NT 8
#define NK 1024
#define NS 8
#define MB 8            // batch rows per CTA (fp16, 8 rows per 16B slot)
#define THREADS 1024    // one k per thread

// 16-bit slot table, layout [s][k][t]: index = (s*NK + k)*NT + t.
// slot = feat*2 + (sign>0 ? 0 : 1); smem byte addr = slot*16.
// With lane = k, each warp's per-s table load is a contiguous 512B block.
__device__ unsigned short g_slot[NS * NK * NT];   // 128 KB

__global__ void prep_kernel(const int* __restrict__ conj_feat,
                            const int* __restrict__ conj_sign,
                            const int* __restrict__ class_conj) {
    int i = blockIdx.x * blockDim.x + threadIdx.x;
    if (i >= NK * NS * NT) return;
    int k = i >> 6;
    int j = i & 63;
    int s = j >> 3;
    int t = j & 7;
    int c    = class_conj[k * NS + s];
    int feat = conj_feat[c * NT + t];
    int sign = conj_sign[c * NT + t];
    g_slot[(s * NK + k) * NT + t] = (unsigned short)(feat * 2 + (sign > 0 ? 0 : 1));
}

static __device__ __forceinline__ unsigned hmul2u(unsigned a, unsigned b) {
    __half2 ha = *reinterpret_cast<__half2*>(&a);
    __half2 hb = *reinterpret_cast<__half2*>(&b);
    __half2 hr = __hmul2(ha, hb);
    return *reinterpret_cast<unsigned*>(&hr);
}
static __device__ __forceinline__ unsigned hmax2u(unsigned a, unsigned b) {
    __half2 ha = *reinterpret_cast<__half2*>(&a);
    __half2 hb = *reinterpret_cast<__half2*>(&b);
    __half2 hr = __hmax2(ha, hb);
    return *reinterpret_cast<unsigned*>(&hr);
}
static __device__ __forceinline__ uint4 mulh8(uint4 a, uint4 b) {
    a.x = hmul2u(a.x, b.x); a.y = hmul2u(a.y, b.y);
    a.z = hmul2u(a.z, b.z); a.w = hmul2u(a.w, b.w);
    return a;
}
static __device__ __forceinline__ uint4 maxh8(uint4 a, uint4 b) {
    a.x = hmax2u(a.x, b.x); a.y = hmax2u(a.y, b.y);
    a.z = hmax2u(a.z, b.z); a.w = hmax2u(a.w, b.w);
    return a;
}
static __device__ __forceinline__ unsigned pack2(float a, float b) {
    __half2 h = __floats2half2_rn(a, b);
    return *reinterpret_cast<unsigned*>(&h);
}

__global__ void __launch_bounds__(THREADS, 1)
dnf_kernel(const float* __restrict__ x, float* __restrict__ out) {
    extern __shared__ unsigned smem_u[];   // [4096 feat][2 var][4 x u32] = 128 KB
    const int b0 = blockIdx.x * MB;

    // Phase A: each thread builds complete 16B slots for feats it owns:
    // 8 coalesced row loads -> pack fp16 -> 2 conflict-free STS.128.
    uint4* slots = (uint4*)smem_u;
    for (int f = threadIdx.x; f < NF; f += THREADS) {
        float v[MB];
        #pragma unroll
        for (int r = 0; r < MB; r++)
            v[r] = x[(size_t)(b0 + r) * NF + f];
        uint4 hx, hn;
        hx.x = pack2(v[0], v[1]);               hn.x = pack2(1.f - v[0], 1.f - v[1]);
        hx.y = pack2(v[2], v[3]);               hn.y = pack2(1.f - v[2], 1.f - v[3]);
        hx.z = pack2(v[4], v[5]);               hn.z = pack2(1.f - v[4], 1.f - v[5]);
        hx.w = pack2(v[6], v[7]);               hn.w = pack2(1.f - v[6], 1.f - v[7]);
        slots[f * 2]     = hx;
        slots[f * 2 + 1] = hn;
    }
    __syncthreads();

    const char* sb = (const char*)smem_u;
    const int k = threadIdx.x;                       // NK == THREADS
    // Table as uint4: one uint4 = 8 slots = one s-group. Stride between s = NK uint4s.
    const uint4* tab = (const uint4*)g_slot + k;     // tab[s*NK]

    uint4 ta = tab[0];                               // s   table
    uint4 tb = tab[NK];                              // s+1 table
    uint4 mx = make_uint4(0u, 0u, 0u, 0u);           // fp16 products >= 0

    #pragma unroll
    for (int s = 0; s < NS; s++) {
        // prefetch s+2 (clamped; redundant loads at tail hit L1)
        int spre = s + 2 < NS - 1 ? s + 2 : NS - 1;
        uint4 tn = tab[spre * NK];

        uint4 q0 = *(const uint4*)(sb + ((ta.x & 0xFFFFu) << 4));
        uint4 q1 = *(const uint4*)(sb + ((ta.x >> 16)     << 4));
        uint4 q2 = *(const uint4*)(sb + ((ta.y & 0xFFFFu) << 4));
        uint4 q3 = *(const uint4*)(sb + ((ta.y >> 16)     << 4));
        uint4 q4 = *(const uint4*)(sb + ((ta.z & 0xFFFFu) << 4));
        uint4 q5 = *(const uint4*)(sb + ((ta.z >> 16)     << 4));
        uint4 q6 = *(const uint4*)(sb + ((ta.w & 0xFFFFu) << 4));
        uint4 q7 = *(const uint4*)(sb + ((ta.w >> 16)     << 4));

        uint4 p = mulh8(mulh8(mulh8(q0, q1), mulh8(q2, q3)),
                        mulh8(mulh8(q4, q5), mulh8(q6, q7)));
        mx = maxh8(mx, p);
        ta = tb;
        tb = tn;
    }

    // Unpack 8 rows and store (coalesced: lanes = consecutive k).
    float2 r01 = __half22float2(*reinterpret_cast<__half2*>(&mx.x));
    float2 r23 = __half22float2(*reinterpret_cast<__half2*>(&mx.y));
    float2 r45 = __half22float2(*reinterpret_cast<__half2*>(&mx.z));
    float2 r67 = __half22float2(*reinterpret_cast<__half2*>(&mx.w));
    out[(size_t)(b0 + 0) * NK + k] = r01.x;
    out[(size_t)(b0 + 1) * NK + k] = r01.y;
    out[(size_t)(b0 + 2) * NK + k] = r23.x;
    out[(size_t)(b0 + 3) * NK + k] = r23.y;
    out[(size_t)(b0 + 4) * NK + k] = r45.x;
    out[(size_t)(b0 + 5) * NK + k] = r45.y;
    out[(size_t)(b0 + 6) * NK + k] = r67.x;
    out[(size_t)(b0 + 7) * NK + k] = r67.y;
}

extern "C" void kernel_launch(void* const* d_in, const int* in_sizes, int n_in,
                              void* d_out, int out_size) {
    const float* x  = (const float*)d_in[0];
    const int*   cf = (const int*)d_in[1];
    const int*   cs = (const int*)d_in[2];
    const int*   cc = (const int*)d_in[3];
    float* out = (float*)d_out;

    prep_kernel<<<(NK * NS * NT + 255) / 256, 256>>>(cf, cs, cc);

    size_t smem_bytes = (size_t)NF * 2 * MB * sizeof(__half);  // 131072
    cudaFuncSetAttribute(dnf_kernel,
                         cudaFuncAttributeMaxDynamicSharedMemorySize,
                         (int)smem_bytes);
    dnf_kernel<<<NB / MB, THREADS, smem_bytes>>>(x, out);
}